// round 16
// baseline (speedup 1.0000x reference)
#include <cuda_runtime.h>
#include <cuda_bf16.h>
#include <math.h>
#include <stdint.h>

#define SEQ_T 256
#define NB    64
#define DIM   512
#define TBM   (SEQ_T * NB * DIM)   /* 8388608 */

// ---------------- scratch (static device memory; no runtime alloc) ----------
__device__ float g_iouT[(size_t)SEQ_T * 4 * DIM * NB];  // [t][gate][m][b]
__device__ float g_ctxT[(size_t)SEQ_T * DIM * NB];      // [t][m][b]
__device__ float g_wcsT[(size_t)SEQ_T * DIM * NB];      // [t][m][b]  (tanh applied)
__device__ float g_hT  [(size_t)SEQ_T * DIM * NB];      // [t][m][b]  h history
__device__ float g_h0T [DIM * NB];                      // [m][b]
__device__ unsigned g_cnt;                              // scan grid-barrier counter

// pre-converted bf16 hi/lo operands
__device__ __align__(16) unsigned short g_Ahi[(size_t)16384 * 1024];
__device__ __align__(16) unsigned short g_Alo[(size_t)16384 * 1024];
__device__ __align__(16) unsigned short g_Wih[(size_t)2048 * 1024];
__device__ __align__(16) unsigned short g_Wil[(size_t)2048 * 1024];
__device__ __align__(16) unsigned short g_Wfh2[512 * 512];
__device__ __align__(16) unsigned short g_Wfl2[512 * 512];
__device__ __align__(16) unsigned short g_Wch2[512 * 512];
__device__ __align__(16) unsigned short g_Wcl2[512 * 512];

typedef unsigned long long ull;

__device__ __forceinline__ void ffma2(ull& d, ull a, ull b) {
    asm("fma.rn.f32x2 %0, %1, %2, %0;" : "+l"(d) : "l"(a), "l"(b));
}
__device__ __forceinline__ ull packdup(float a) {
    ull r; asm("mov.b64 %0, {%1, %1};" : "=l"(r) : "f"(a)); return r;
}
__device__ __forceinline__ float tanh_fast(float x) {
    float y; asm("tanh.approx.f32 %0, %1;" : "=f"(y) : "f"(x)); return y;
}
__device__ __forceinline__ float sigmoid_fast(float x) {
    return fmaf(0.5f, tanh_fast(0.5f * x), 0.5f);
}
__device__ __forceinline__ uint32_t smem_u32(const void* p) {
    uint32_t a;
    asm("{ .reg .u64 t; cvta.to.shared.u64 t, %1; cvt.u32.u64 %0, t; }" : "=r"(a) : "l"(p));
    return a;
}
__device__ __forceinline__ void ldsm4(uint32_t* r, uint32_t addr) {
    asm volatile("ldmatrix.sync.aligned.m8n8.x4.shared.b16 {%0,%1,%2,%3}, [%4];"
                 : "=r"(r[0]), "=r"(r[1]), "=r"(r[2]), "=r"(r[3]) : "r"(addr));
}
__device__ __forceinline__ void mma_bf16(float* d, const uint32_t* a, const uint32_t* b) {
    asm volatile(
        "mma.sync.aligned.m16n8k16.row.col.f32.bf16.bf16.f32 "
        "{%0,%1,%2,%3}, {%4,%5,%6,%7}, {%8,%9}, {%0,%1,%2,%3};"
        : "+f"(d[0]), "+f"(d[1]), "+f"(d[2]), "+f"(d[3])
        : "r"(a[0]), "r"(a[1]), "r"(a[2]), "r"(a[3]), "r"(b[0]), "r"(b[1]));
}
__device__ __forceinline__ void cp16(uint32_t dst, const void* src) {
    asm volatile("cp.async.ca.shared.global [%0], [%1], 16;" :: "r"(dst), "l"(src));
}

// ---------------------------------------------------------------------------
// Fused conversion + init (one launch).
// ---------------------------------------------------------------------------
__device__ __forceinline__ void conv_body(
    const float4* __restrict__ src, unsigned short* __restrict__ hi,
    unsigned short* __restrict__ lo, int dst_pitch, int col_off, int idx)
{
    int r  = idx >> 7;
    int c4 = (idx & 127) << 2;
    float4 v = __ldg(src + idx);
    __nv_bfloat16 h0 = __float2bfloat16_rn(v.x);
    __nv_bfloat16 h1 = __float2bfloat16_rn(v.y);
    __nv_bfloat16 h2 = __float2bfloat16_rn(v.z);
    __nv_bfloat16 h3 = __float2bfloat16_rn(v.w);
    __nv_bfloat16 l0 = __float2bfloat16_rn(v.x - __bfloat162float(h0));
    __nv_bfloat16 l1 = __float2bfloat16_rn(v.y - __bfloat162float(h1));
    __nv_bfloat16 l2 = __float2bfloat16_rn(v.z - __bfloat162float(h2));
    __nv_bfloat16 l3 = __float2bfloat16_rn(v.w - __bfloat162float(h3));
    uint2 hp, lp;
    hp.x = ((unsigned)__bfloat16_as_ushort(h1) << 16) | __bfloat16_as_ushort(h0);
    hp.y = ((unsigned)__bfloat16_as_ushort(h3) << 16) | __bfloat16_as_ushort(h2);
    lp.x = ((unsigned)__bfloat16_as_ushort(l1) << 16) | __bfloat16_as_ushort(l0);
    lp.y = ((unsigned)__bfloat16_as_ushort(l3) << 16) | __bfloat16_as_ushort(l2);
    size_t d = (size_t)r * dst_pitch + col_off + c4;
    *reinterpret_cast<uint2*>(hi + d) = hp;
    *reinterpret_cast<uint2*>(lo + d) = lp;
}

__global__ void __launch_bounds__(256) conv_init_kernel(
    const float* __restrict__ inputs, const float* __restrict__ emb_s,
    const float* __restrict__ W_ioux, const float* __restrict__ W_ious,
    const float* __restrict__ W_fx,   const float* __restrict__ W_wc,
    const float* __restrict__ h0)
{
    const int b = blockIdx.x;
    const int tid = threadIdx.x;
    if (b < 8192) {
        conv_body((const float4*)inputs, g_Ahi, g_Alo, 1024, 0, b * 256 + tid);
    } else if (b < 16384) {
        conv_body((const float4*)emb_s, g_Ahi, g_Alo, 1024, 512, (b - 8192) * 256 + tid);
    } else if (b < 17408) {
        conv_body((const float4*)W_ioux, g_Wih, g_Wil, 1024, 0, (b - 16384) * 256 + tid);
    } else if (b < 18432) {
        conv_body((const float4*)W_ious, g_Wih, g_Wil, 1024, 512, (b - 17408) * 256 + tid);
    } else if (b < 18688) {
        conv_body((const float4*)W_fx, g_Wfh2, g_Wfl2, 512, 0, (b - 18432) * 256 + tid);
    } else if (b < 18944) {
        conv_body((const float4*)W_wc, g_Wch2, g_Wcl2, 512, 0, (b - 18688) * 256 + tid);
    } else {
        int bb = b - 18944;                       // 0..63 (batch)
        for (int i = tid; i < 512; i += 256)
            g_h0T[i * 64 + bb] = h0[bb * 512 + i];
        if (bb == 0 && tid == 0) g_cnt = 0u;
    }
}

// ---------------------------------------------------------------------------
// HMMA GEMM on pre-converted bf16 (split hi+lo, fp32 accum), cp.async
// 3-stage pipelined, K-chunk 64. 512 threads, 16 warps, warp tile 32x32.
// ---------------------------------------------------------------------------
#define GT_TILE  18432                /* 128 rows * 144B */
#define GT_BUF   (4 * GT_TILE)        /* 73728 */
#define GT_A_HI  0
#define GT_A_LO  GT_TILE
#define GT_B_HI  (2 * GT_TILE)
#define GT_B_LO  (3 * GT_TILE)
#define G_SMEM_TOTAL (3 * GT_BUF)     /* 221184; epilogue (128*136*4=69632) reuses */

__global__ void __launch_bounds__(512) gemm_tc_kernel(
    const float* __restrict__ b_ioux, const float* __restrict__ b_ious,
    const float* __restrict__ b_fx,   const float* __restrict__ b_wc)
{
    extern __shared__ char smem[];
    __shared__ float bias_sm[128];
    const uint32_t sbase = smem_u32(smem);

    const int tid  = threadIdx.x;
    const int wid  = tid >> 5;
    const int lane = tid & 31;
    const int blk  = blockIdx.x;

    int mode, bx, by, K, acol0, bpitch;
    const unsigned short *Bh, *Bl;
    if (blk < 2048) {
        mode = 0; bx = blk & 15; by = blk >> 4; K = 1024; acol0 = 0;
        Bh = g_Wih; Bl = g_Wil; bpitch = 1024;
    } else if (blk < 2560) {
        int l = blk - 2048;
        mode = 1; bx = l & 3; by = l >> 2; K = 512; acol0 = 0;
        Bh = g_Wfh2; Bl = g_Wfl2; bpitch = 512;
    } else {
        int l = blk - 2560;
        mode = 2; bx = l & 3; by = l >> 2; K = 512; acol0 = 512;
        Bh = g_Wch2; Bl = g_Wcl2; bpitch = 512;
    }
    const int bm = by * 128;
    const int bn = bx * 128;
    const int t0 = bm >> 6;

    if (tid < 128) {
        float v;
        if (mode == 0)      v = b_ioux[bn + tid] + b_ious[bn + tid];
        else if (mode == 1) v = b_fx[bn + tid];
        else                v = b_wc[bn + tid];
        bias_sm[tid] = v;
    }

    const int m0 = (wid & 3) * 32;
    const int n0 = (wid >> 2) * 32;

    float acc[2][4][4];
    #pragma unroll
    for (int i = 0; i < 2; i++)
        #pragma unroll
        for (int j = 0; j < 4; j++)
            #pragma unroll
            for (int e = 0; e < 4; e++) acc[i][j][e] = 0.f;

    const uint32_t aoff = (uint32_t)((lane & 15) * 144 + (lane >> 4) * 16);
    const uint32_t boff = (uint32_t)((((lane >> 4) << 3) + (lane & 7)) * 144 + ((lane >> 3) & 1) * 16);

    const int sr = tid >> 3;
    const int sq = tid & 7;

    const int nc = K >> 6;

    // prologue: stage chunks 0 and 1 (each its own commit group)
    #pragma unroll
    for (int pc = 0; pc < 2; pc++) {
        const int kg = pc * 64;
        uint32_t d0 = sbase + pc * GT_BUF;
        #pragma unroll
        for (int i = 0; i < 2; i++) {
            int r = sr + i * 64;
            uint32_t d = d0 + (uint32_t)(r * 144 + sq * 16);
            cp16(d + GT_A_HI, (const char*)(g_Ahi + (size_t)(bm + r) * 1024 + acol0 + kg) + sq * 16);
            cp16(d + GT_A_LO, (const char*)(g_Alo + (size_t)(bm + r) * 1024 + acol0 + kg) + sq * 16);
            cp16(d + GT_B_HI, (const char*)(Bh + (size_t)(bn + r) * bpitch + kg) + sq * 16);
            cp16(d + GT_B_LO, (const char*)(Bl + (size_t)(bn + r) * bpitch + kg) + sq * 16);
        }
        asm volatile("cp.async.commit_group;");
    }

    int pw = 2;                        // next buffer slot to write (round-robin 0..2)
    for (int c = 0; c < nc; c++) {
        const uint32_t bufb = sbase + (c % 3) * GT_BUF;

        // stage chunk c+2 (or an empty group to keep the count uniform)
        if (c + 2 < nc) {
            const int kg = (c + 2) * 64;
            uint32_t d0 = sbase + pw * GT_BUF;
            #pragma unroll
            for (int i = 0; i < 2; i++) {
                int r = sr + i * 64;
                uint32_t d = d0 + (uint32_t)(r * 144 + sq * 16);
                cp16(d + GT_A_HI, (const char*)(g_Ahi + (size_t)(bm + r) * 1024 + acol0 + kg) + sq * 16);
                cp16(d + GT_A_LO, (const char*)(g_Alo + (size_t)(bm + r) * 1024 + acol0 + kg) + sq * 16);
                cp16(d + GT_B_HI, (const char*)(Bh + (size_t)(bn + r) * bpitch + kg) + sq * 16);
                cp16(d + GT_B_LO, (const char*)(Bl + (size_t)(bn + r) * bpitch + kg) + sq * 16);
            }
        }
        asm volatile("cp.async.commit_group;");
        asm volatile("cp.async.wait_group 2;");   // chunk c's group complete
        __syncthreads();
        pw = (pw + 1 == 3) ? 0 : pw + 1;

        #pragma unroll
        for (int s = 0; s < 4; s++) {
            const uint32_t kkb = s * 32;
            uint32_t a_h[2][4], a_l[2][4], b_h[2][4], b_l[2][4];
            #pragma unroll
            for (int mt = 0; mt < 2; mt++) {
                uint32_t ad = bufb + (uint32_t)((m0 + mt * 16) * 144) + aoff + kkb;
                ldsm4(a_h[mt], ad + GT_A_HI);
                ldsm4(a_l[mt], ad + GT_A_LO);
            }
            #pragma unroll
            for (int pq = 0; pq < 2; pq++) {
                uint32_t bd = bufb + (uint32_t)((n0 + pq * 16) * 144) + boff + kkb;
                ldsm4(b_h[pq], bd + GT_B_HI);
                ldsm4(b_l[pq], bd + GT_B_LO);
            }
            #pragma unroll
            for (int mt = 0; mt < 2; mt++) {
                #pragma unroll
                for (int nt = 0; nt < 4; nt++) {
                    const uint32_t* bh = &b_h[nt >> 1][(nt & 1) * 2];
                    const uint32_t* bl = &b_l[nt >> 1][(nt & 1) * 2];
                    mma_bf16(acc[mt][nt], a_h[mt], bh);
                    mma_bf16(acc[mt][nt], a_h[mt], bl);
                    mma_bf16(acc[mt][nt], a_l[mt], bh);
                }
            }
        }
        __syncthreads();
    }

    float* ep = reinterpret_cast<float*>(smem);
    #pragma unroll
    for (int mt = 0; mt < 2; mt++)
        #pragma unroll
        for (int nt = 0; nt < 4; nt++)
            #pragma unroll
            for (int e = 0; e < 4; e++) {
                int m = m0 + mt * 16 + (lane >> 2) + (e >> 1) * 8;
                int n = n0 + nt * 8 + (lane & 3) * 2 + (e & 1);
                float v = acc[mt][nt][e] + bias_sm[n];
                if (mode == 2) v = tanhf(v);
                ep[n * 136 + m] = v;
            }
    __syncthreads();

    #pragma unroll
    for (int i = 0; i < 8; i++) {
        int q   = tid + i * 512;
        int col = q >> 5;
        int f4  = q & 31;
        int m   = f4 * 4;
        float4 val = *reinterpret_cast<float4*>(ep + col * 136 + m);
        int cn = bn + col;
        int t  = t0 + (m >> 6);
        int b  = m & 63;
        float* dst;
        if (mode == 0)
            dst = g_iouT + (((size_t)t * 4 + (cn >> 9)) * 512 + (cn & 511)) * 64 + b;
        else if (mode == 1)
            dst = g_ctxT + ((size_t)t * 512 + cn) * 64 + b;
        else
            dst = g_wcsT + ((size_t)t * 512 + cn) * 64 + b;
        *reinterpret_cast<float4*>(dst) = val;
    }
}

// ---------------------------------------------------------------------------
// Persistent scan (R12 exact): kc-skewed weights, FFMA2, flat atomic barrier.
// ---------------------------------------------------------------------------
#define SM4_FLOATS 8256
#define SM1_FLOATS 2080
#define SM4_BYTES  (SM4_FLOATS * 4)
#define SM1_BYTES  (SM1_FLOATS * 4)
#define BUF_BYTES  20480
#define SCAN_SMEM_BYTES (SM4_BYTES + SM1_BYTES + BUF_BYTES)   /* 61824 */

__global__ void __launch_bounds__(256) scan_kernel(
    const float* __restrict__ W_iouh, const float* __restrict__ b_iouh,
    const float* __restrict__ W_fh,   const float* __restrict__ b_fh,
    const float* __restrict__ c0,     float* __restrict__ out)
{
    extern __shared__ char smraw[];
    float4* sm4w = reinterpret_cast<float4*>(smraw);
    float2* sm1w = reinterpret_cast<float2*>(smraw + SM4_BYTES);
    ull*    buf  = reinterpret_cast<ull*>(smraw + SM4_BYTES + SM1_BYTES);

    const int tid  = threadIdx.x;
    const int warp = tid >> 5;
    const int lane = tid & 31;
    const int mp   = warp >> 2;
    const int iq   = warp & 3;
    const int kc   = lane >> 3;
    const int bq   = lane & 7;
    const int blk  = blockIdx.x;

    for (int idx = tid; idx < 2048; idx += 256) {
        int ml = idx >> 9;
        int k  = idx & 511;
        int mg = blk * 4 + ml;
        sm4w[ml * 516 + (k >> 7) * 129 + (k & 127)] = make_float4(
            W_iouh[(size_t)mg * 512 + k],
            W_iouh[(size_t)(512 + mg) * 512 + k],
            W_iouh[(size_t)(1024 + mg) * 512 + k],
            W_iouh[(size_t)(1536 + mg) * 512 + k]);
    }
    for (int idx = tid; idx < 1024; idx += 256) {
        int mpp = idx >> 9;
        int k   = idx & 511;
        int mg0 = blk * 4 + 2 * mpp;
        sm1w[mpp * 520 + (k >> 7) * 130 + (k & 127)] =
            make_float2(W_fh[(size_t)mg0 * 512 + k], W_fh[(size_t)(mg0 + 1) * 512 + k]);
    }
    __syncthreads();

    const int m_own = tid >> 5;
    const int b0    = 2 * (tid & 31);
    const int m_g   = blk * 4 + m_own;
    const int mp_o  = m_own >> 1;
    const int ml_o  = m_own & 1;
    int bq_o, pr_o;
    if (b0 < 32) { bq_o = b0 >> 2; pr_o = (b0 >> 1) & 1; }
    else         { int bb = b0 - 32; bq_o = bb >> 2; pr_o = 2 + ((bb >> 1) & 1); }

    float bfv = 0.f, biv = 0.f, bov = 0.f, bocv = 0.f, bfhv = 0.f;
    float2 c_reg = make_float2(0.f, 0.f);
    float2 af2, ai2, ao2, aoc2, act2, aw2;
    if (tid < 128) {
        bfv  = b_iouh[m_g];
        biv  = b_iouh[512 + m_g];
        bov  = b_iouh[1024 + m_g];
        bocv = b_iouh[1536 + m_g];
        bfhv = b_fh[m_g];
        c_reg.x = c0[(size_t)b0 * 512 + m_g];
        c_reg.y = c0[(size_t)(b0 + 1) * 512 + m_g];
        const size_t ib = ((size_t)0 * 4 * 512 + m_g) * 64 + b0;
        const size_t sb = (size_t)m_g * 64 + b0;
        af2  = *reinterpret_cast<const float2*>(&g_iouT[ib]);
        ai2  = *reinterpret_cast<const float2*>(&g_iouT[ib + 1 * 512 * 64]);
        ao2  = *reinterpret_cast<const float2*>(&g_iouT[ib + 2 * 512 * 64]);
        aoc2 = *reinterpret_cast<const float2*>(&g_iouT[ib + 3 * 512 * 64]);
        act2 = *reinterpret_cast<const float2*>(&g_ctxT[sb]);
        aw2  = *reinterpret_cast<const float2*>(&g_wcsT[sb]);
    }

    const int kbase = kc * 128 + iq * 32;
    const int fbase = kbase * 16 + bq;
    const int w4base = kc * 129 + iq * 32;
    const int w1base = kc * 130 + iq * 32;
    float2 h_keep = make_float2(0.f, 0.f);

    for (int t = 0; t < SEQ_T; t++) {
        const float* hb = (t == 0) ? g_h0T : (g_hT + (size_t)(t - 1) * (DIM * NB));
        const float4* hp = reinterpret_cast<const float4*>(hb);

        ull A[2][5][4];
        #pragma unroll
        for (int a1 = 0; a1 < 2; a1++)
            #pragma unroll
            for (int a2 = 0; a2 < 5; a2++)
                #pragma unroll
                for (int a3 = 0; a3 < 4; a3++) A[a1][a2][a3] = 0ull;

        #pragma unroll 4
        for (int i = 0; i < 32; i++) {
            float4 hl = __ldg(hp + fbase + i * 16);
            float4 hh = __ldg(hp + fbase + 8 + i * 16);
            ull hpair[4];
            hpair[0] = reinterpret_cast<ulonglong2*>(&hl)->x;
            hpair[1] = reinterpret_cast<ulonglong2*>(&hl)->y;
            hpair[2] = reinterpret_cast<ulonglong2*>(&hh)->x;
            hpair[3] = reinterpret_cast<ulonglong2*>(&hh)->y;

            float wa[10];
            *reinterpret_cast<float4*>(wa + 0) = sm4w[(mp * 2 + 0) * 516 + w4base + i];
            *reinterpret_cast<float4*>(wa + 4) = sm4w[(mp * 2 + 1) * 516 + w4base + i];
            *reinterpret_cast<float2*>(wa + 8) = sm1w[mp * 520 + w1base + i];

            #pragma unroll
            for (int ml = 0; ml < 2; ml++) {
                #pragma unroll
                for (int g = 0; g < 5; g++) {
                    float w = (g < 4) ? wa[ml * 4 + g] : wa[8 + ml];
                    ull wd = packdup(w);
                    #pragma unroll
                    for (int pr = 0; pr < 4; pr++)
                        ffma2(A[ml][g][pr], hpair[pr], wd);
                }
            }
        }

        ull* Af = &A[0][0][0];
        #pragma unroll
        for (int c = 0; c < 40; c++) {
            float2 v = *reinterpret_cast<float2*>(&Af[c]);
            v.x += __shfl_xor_sync(0xffffffffu, v.x, 8);
            v.y += __shfl_xor_sync(0xffffffffu, v.y, 8);
            v.x += __shfl_xor_sync(0xffffffffu, v.x, 16);
            v.y += __shfl_xor_sync(0xffffffffu, v.y, 16);
            Af[c] = *reinterpret_cast<ull*>(&v);
        }

        #pragma unroll
        for (int cc = 0; cc < 10; cc++) {
            int c = kc * 10 + cc;
            buf[((size_t)warp * 40 + c) * 8 + bq] = Af[c];
        }
        __syncthreads();

        if (tid < 128) {
            float2 s[5];
            #pragma unroll
            for (int g = 0; g < 5; g++) {
                int c = ml_o * 20 + g * 4 + pr_o;
                float2 acc2 = make_float2(0.f, 0.f);
                #pragma unroll
                for (int q = 0; q < 4; q++) {
                    ull v = buf[((size_t)(mp_o * 4 + q) * 40 + c) * 8 + bq_o];
                    float2 f = *reinterpret_cast<float2*>(&v);
                    acc2.x += f.x; acc2.y += f.y;
                }
                s[g] = acc2;
            }

            float fgx  = sigmoid_fast(s[0].x + af2.x + bfv);
            float fgy  = sigmoid_fast(s[0].y + af2.y + bfv);
            float igx  = sigmoid_fast(s[1].x + ai2.x + biv);
            float igy  = sigmoid_fast(s[1].y + ai2.y + biv);
            float ogx  = sigmoid_fast(s[2].x + ao2.x + bov);
            float ogy  = sigmoid_fast(s[2].y + ao2.y + bov);
            float ocgx = sigmoid_fast(s[3].x + aoc2.x + bocv);
            float ocgy = sigmoid_fast(s[3].y + aoc2.y + bocv);
            float ctx_ = tanh_fast(s[4].x + act2.x + bfhv);
            float cty_ = tanh_fast(s[4].y + act2.y + bfhv);

            c_reg.x = igx * ctx_ + fgx * c_reg.x;
            c_reg.y = igy * cty_ + fgy * c_reg.y;
            h_keep.x = ogx * tanh_fast(c_reg.x) + ocgx * aw2.x;
            h_keep.y = ogy * tanh_fast(c_reg.y) + ocgy * aw2.y;

            *reinterpret_cast<float2*>(&g_hT[(size_t)t * (DIM * NB) + (size_t)m_g * 64 + b0]) = h_keep;
            out[(size_t)t * (NB * DIM) + (size_t)b0 * 512 + m_g]       = h_keep.x;
            out[(size_t)t * (NB * DIM) + (size_t)(b0 + 1) * 512 + m_g] = h_keep.y;

            if (t + 1 < SEQ_T) {
                const size_t ib2 = (((size_t)(t + 1) * 4) * 512 + m_g) * 64 + b0;
                const size_t sb2 = (size_t)(t + 1) * (512 * 64) + (size_t)m_g * 64 + b0;
                af2  = *reinterpret_cast<const float2*>(&g_iouT[ib2]);
                ai2  = *reinterpret_cast<const float2*>(&g_iouT[ib2 + 1 * 512 * 64]);
                ao2  = *reinterpret_cast<const float2*>(&g_iouT[ib2 + 2 * 512 * 64]);
                aoc2 = *reinterpret_cast<const float2*>(&g_iouT[ib2 + 3 * 512 * 64]);
                act2 = *reinterpret_cast<const float2*>(&g_ctxT[sb2]);
                aw2  = *reinterpret_cast<const float2*>(&g_wcsT[sb2]);
            }
        }

        __syncthreads();
        if (tid == 0) {
            __threadfence();
            atomicAdd(&g_cnt, 1u);
            const unsigned target = (unsigned)gridDim.x * (unsigned)(t + 1);
            while (*reinterpret_cast<volatile unsigned*>(&g_cnt) < target) { }
            __threadfence();
        }
        __syncthreads();
    }

    if (tid < 128) {
        out[TBM + (size_t)b0 * 512 + m_g]                  = c_reg.x;
        out[TBM + (size_t)(b0 + 1) * 512 + m_g]            = c_reg.y;
        out[TBM + NB * DIM + (size_t)b0 * 512 + m_g]       = h_keep.x;
        out[TBM + NB * DIM + (size_t)(b0 + 1) * 512 + m_g] = h_keep.y;
    }
}

// ---------------------------------------------------------------------------
extern "C" void kernel_launch(void* const* d_in, const int* in_sizes, int n_in,
                              void* d_out, int out_size)
{
    const float* inputs = (const float*)d_in[0];
    const float* emb_s  = (const float*)d_in[1];
    const float* c0     = (const float*)d_in[2];
    const float* h0     = (const float*)d_in[3];
    const float* W_ioux = (const float*)d_in[4];
    const float* b_ioux = (const float*)d_in[5];
    const float* W_iouh = (const float*)d_in[6];
    const float* b_iouh = (const float*)d_in[7];
    const float* W_ious = (const float*)d_in[8];
    const float* b_ious = (const float*)d_in[9];
    const float* W_fx   = (const float*)d_in[10];
    const float* b_fx   = (const float*)d_in[11];
    const float* W_fh   = (const float*)d_in[12];
    const float* b_fh   = (const float*)d_in[13];
    const float* W_wc   = (const float*)d_in[14];
    const float* b_wc   = (const float*)d_in[15];
    float* out = (float*)d_out;

    static int smem_set = 0;
    if (!smem_set) {
        cudaFuncSetAttribute(scan_kernel, cudaFuncAttributeMaxDynamicSharedMemorySize,
                             SCAN_SMEM_BYTES);
        cudaFuncSetAttribute(gemm_tc_kernel, cudaFuncAttributeMaxDynamicSharedMemorySize,
                             G_SMEM_TOTAL);
        smem_set = 1;
    }

    conv_init_kernel<<<19008, 256>>>(inputs, emb_s, W_ioux, W_ious, W_fx, W_wc, h0);
    gemm_tc_kernel<<<3072, 512, G_SMEM_TOTAL>>>(b_ioux, b_ious, b_fx, b_wc);
    scan_kernel<<<128, 256, SCAN_SMEM_BYTES>>>(W_iouh, b_iouh, W_fh, b_fh, c0, out);
}

// round 17
// speedup vs baseline: 1.1426x; 1.1426x over previous
#include <cuda_runtime.h>
#include <cuda_bf16.h>
#include <math.h>
#include <stdint.h>

#define SEQ_T 256
#define NB    64
#define DIM   512
#define TBM   (SEQ_T * NB * DIM)   /* 8388608 */

// ---------------- scratch (static device memory; no runtime alloc) ----------
__device__ float g_iouT[(size_t)SEQ_T * 4 * DIM * NB];  // [t][gate][m][b]
__device__ float g_ctxT[(size_t)SEQ_T * DIM * NB];      // [t][m][b]
__device__ float g_wcsT[(size_t)SEQ_T * DIM * NB];      // [t][m][b]  (tanh applied)
__device__ float g_hT  [(size_t)SEQ_T * DIM * NB];      // [t][m][b]  h history
__device__ float g_h0T [DIM * NB];                      // [m][b]
__device__ unsigned g_cnt;                              // scan grid-barrier counter

// pre-converted tf32 operands (stored as 32-bit words, cvt.rna applied)
__device__ __align__(16) float g_Atf[(size_t)16384 * 1024];   // [inputs | emb_s]
__device__ __align__(16) float g_Wtf[(size_t)2048 * 1024];    // [W_ioux | W_ious]
__device__ __align__(16) float g_Wftf[512 * 512];
__device__ __align__(16) float g_Wctf[512 * 512];

typedef unsigned long long ull;

__device__ __forceinline__ void ffma2(ull& d, ull a, ull b) {
    asm("fma.rn.f32x2 %0, %1, %2, %0;" : "+l"(d) : "l"(a), "l"(b));
}
__device__ __forceinline__ ull packdup(float a) {
    ull r; asm("mov.b64 %0, {%1, %1};" : "=l"(r) : "f"(a)); return r;
}
__device__ __forceinline__ float tanh_fast(float x) {
    float y; asm("tanh.approx.f32 %0, %1;" : "=f"(y) : "f"(x)); return y;
}
__device__ __forceinline__ float sigmoid_fast(float x) {
    return fmaf(0.5f, tanh_fast(0.5f * x), 0.5f);
}
__device__ __forceinline__ uint32_t smem_u32(const void* p) {
    uint32_t a;
    asm("{ .reg .u64 t; cvta.to.shared.u64 t, %1; cvt.u32.u64 %0, t; }" : "=r"(a) : "l"(p));
    return a;
}
__device__ __forceinline__ uint32_t to_tf32(float x) {
    uint32_t r; asm("cvt.rna.tf32.f32 %0, %1;" : "=r"(r) : "f"(x)); return r;
}
__device__ __forceinline__ void ldsm4(uint32_t* r, uint32_t addr) {
    asm volatile("ldmatrix.sync.aligned.m8n8.x4.shared.b16 {%0,%1,%2,%3}, [%4];"
                 : "=r"(r[0]), "=r"(r[1]), "=r"(r[2]), "=r"(r[3]) : "r"(addr));
}
__device__ __forceinline__ void mma_tf32(float* d, const uint32_t* a, const uint32_t* b) {
    asm volatile(
        "mma.sync.aligned.m16n8k8.row.col.f32.tf32.tf32.f32 "
        "{%0,%1,%2,%3}, {%4,%5,%6,%7}, {%8,%9}, {%0,%1,%2,%3};"
        : "+f"(d[0]), "+f"(d[1]), "+f"(d[2]), "+f"(d[3])
        : "r"(a[0]), "r"(a[1]), "r"(a[2]), "r"(a[3]), "r"(b[0]), "r"(b[1]));
}
__device__ __forceinline__ void cp16(uint32_t dst, const void* src) {
    asm volatile("cp.async.ca.shared.global [%0], [%1], 16;" :: "r"(dst), "l"(src));
}

// ---------------------------------------------------------------------------
// Fused conversion + init (one launch): fp32 -> tf32 words.
// ---------------------------------------------------------------------------
__device__ __forceinline__ void conv_body(
    const float4* __restrict__ src, float* __restrict__ dst,
    int dst_pitch, int col_off, int idx)
{
    int r  = idx >> 7;
    int c4 = (idx & 127) << 2;
    float4 v = __ldg(src + idx);
    uint4 o;
    o.x = to_tf32(v.x);
    o.y = to_tf32(v.y);
    o.z = to_tf32(v.z);
    o.w = to_tf32(v.w);
    *reinterpret_cast<uint4*>(dst + (size_t)r * dst_pitch + col_off + c4) = o;
}

__global__ void __launch_bounds__(256) conv_init_kernel(
    const float* __restrict__ inputs, const float* __restrict__ emb_s,
    const float* __restrict__ W_ioux, const float* __restrict__ W_ious,
    const float* __restrict__ W_fx,   const float* __restrict__ W_wc,
    const float* __restrict__ h0)
{
    const int b = blockIdx.x;
    const int tid = threadIdx.x;
    if (b < 8192) {
        conv_body((const float4*)inputs, g_Atf, 1024, 0, b * 256 + tid);
    } else if (b < 16384) {
        conv_body((const float4*)emb_s, g_Atf, 1024, 512, (b - 8192) * 256 + tid);
    } else if (b < 17408) {
        conv_body((const float4*)W_ioux, g_Wtf, 1024, 0, (b - 16384) * 256 + tid);
    } else if (b < 18432) {
        conv_body((const float4*)W_ious, g_Wtf, 1024, 512, (b - 17408) * 256 + tid);
    } else if (b < 18688) {
        conv_body((const float4*)W_fx, g_Wftf, 512, 0, (b - 18432) * 256 + tid);
    } else if (b < 18944) {
        conv_body((const float4*)W_wc, g_Wctf, 512, 0, (b - 18688) * 256 + tid);
    } else {
        int bb = b - 18944;                       // 0..63 (batch)
        for (int i = tid; i < 512; i += 256)
            g_h0T[i * 64 + bb] = h0[bb * 512 + i];
        if (bb == 0 && tid == 0) g_cnt = 0u;
    }
}

// ---------------------------------------------------------------------------
// TF32 HMMA GEMM (single pass, fp32 accum), cp.async double-buffered,
// K-chunk 32. 512 threads, 16 warps, warp tile 32x32.
//   blocks [0,2048)    : iou_x  (N=2048, K=1024)
//   blocks [2048,2560) : ctx    (N=512,  K=512)
//   blocks [2560,3072) : wcs    (N=512,  K=512, tanh epilogue)
// SMEM tile: 128 rows * 144B (32 tf32 + 16B pad; ldmatrix conflict-free).
// ---------------------------------------------------------------------------
#define GT_TILE  18432                /* 128 rows * 144B */
#define GT_BUF   (2 * GT_TILE)        /* A + B = 36864 */
#define G_SMEM_TOTAL (2 * GT_BUF)     /* 73728; epilogue (128*136*4=69632) reuses */

__global__ void __launch_bounds__(512) gemm_tc_kernel(
    const float* __restrict__ b_ioux, const float* __restrict__ b_ious,
    const float* __restrict__ b_fx,   const float* __restrict__ b_wc)
{
    extern __shared__ char smem[];
    __shared__ float bias_sm[128];
    const uint32_t sbase = smem_u32(smem);

    const int tid  = threadIdx.x;
    const int wid  = tid >> 5;
    const int lane = tid & 31;
    const int blk  = blockIdx.x;

    int mode, bx, by, K, acol0, bpitch;
    const float *Bp;
    if (blk < 2048) {
        mode = 0; bx = blk & 15; by = blk >> 4; K = 1024; acol0 = 0;
        Bp = g_Wtf; bpitch = 1024;
    } else if (blk < 2560) {
        int l = blk - 2048;
        mode = 1; bx = l & 3; by = l >> 2; K = 512; acol0 = 0;
        Bp = g_Wftf; bpitch = 512;
    } else {
        int l = blk - 2560;
        mode = 2; bx = l & 3; by = l >> 2; K = 512; acol0 = 512;
        Bp = g_Wctf; bpitch = 512;
    }
    const int bm = by * 128;
    const int bn = bx * 128;
    const int t0 = bm >> 6;

    if (tid < 128) {
        float v;
        if (mode == 0)      v = b_ioux[bn + tid] + b_ious[bn + tid];
        else if (mode == 1) v = b_fx[bn + tid];
        else                v = b_wc[bn + tid];
        bias_sm[tid] = v;
    }

    const int m0 = (wid & 3) * 32;
    const int n0 = (wid >> 2) * 32;

    float acc[2][4][4];
    #pragma unroll
    for (int i = 0; i < 2; i++)
        #pragma unroll
        for (int j = 0; j < 4; j++)
            #pragma unroll
            for (int e = 0; e < 4; e++) acc[i][j][e] = 0.f;

    // tf32 ldmatrix per-lane offsets (within a 16-row fragment tile)
    // A: matrices [rows0-7,c0-3][rows8-15,c0-3][rows0-7,c4-7][rows8-15,c4-7]
    const uint32_t aoff = (uint32_t)(((lane & 7) + ((lane >> 3) & 1) * 8) * 144 + (lane >> 4) * 16);
    // B: matrices [n0-7,k0-3][n0-7,k4-7][n8-15,k0-3][n8-15,k4-7]
    const uint32_t boff = (uint32_t)(((lane & 7) + ((lane >> 4) & 1) * 8) * 144 + ((lane >> 3) & 1) * 16);

    const int sr = tid >> 2;          // not used; staging below uses idx decode
    (void)sr;

    const int nc = K >> 5;            // chunks of 32 tf32 cols (128B rows)

    // stage chunk 0
    {
        const int kg = 0;
        #pragma unroll
        for (int i = 0; i < 2; i++) {
            int idx = tid + i * 512;          // 0..1023
            int r   = idx >> 3;
            int q   = idx & 7;
            uint32_t d = sbase + (uint32_t)(r * 144 + q * 16);
            cp16(d, (const char*)(g_Atf + (size_t)(bm + r) * 1024 + acol0 + kg) + q * 16);
            cp16(d + GT_TILE, (const char*)(Bp + (size_t)(bn + r) * bpitch + kg) + q * 16);
        }
        asm volatile("cp.async.commit_group;");
    }

    for (int c = 0; c < nc; c++) {
        const int p = c & 1;
        const uint32_t bufb = sbase + p * GT_BUF;

        if (c + 1 < nc) {
            const int kg = (c + 1) * 32;
            uint32_t d0 = sbase + (p ^ 1) * GT_BUF;
            #pragma unroll
            for (int i = 0; i < 2; i++) {
                int idx = tid + i * 512;
                int r   = idx >> 3;
                int q   = idx & 7;
                uint32_t d = d0 + (uint32_t)(r * 144 + q * 16);
                cp16(d, (const char*)(g_Atf + (size_t)(bm + r) * 1024 + acol0 + kg) + q * 16);
                cp16(d + GT_TILE, (const char*)(Bp + (size_t)(bn + r) * bpitch + kg) + q * 16);
            }
            asm volatile("cp.async.commit_group;");
            asm volatile("cp.async.wait_group 1;");
        } else {
            asm volatile("cp.async.wait_group 0;");
        }
        __syncthreads();

        #pragma unroll
        for (int s = 0; s < 4; s++) {
            const uint32_t kkb = s * 32;      // 8 tf32 = 32B per k8 step
            uint32_t a[2][4], b[2][4];
            #pragma unroll
            for (int mt = 0; mt < 2; mt++)
                ldsm4(a[mt], bufb + (uint32_t)((m0 + mt * 16) * 144) + aoff + kkb);
            #pragma unroll
            for (int pq = 0; pq < 2; pq++)
                ldsm4(b[pq], bufb + GT_TILE + (uint32_t)((n0 + pq * 16) * 144) + boff + kkb);
            #pragma unroll
            for (int mt = 0; mt < 2; mt++) {
                #pragma unroll
                for (int nt = 0; nt < 4; nt++)
                    mma_tf32(acc[mt][nt], a[mt], &b[nt >> 1][(nt & 1) * 2]);
            }
        }
        __syncthreads();
    }

    // ---- epilogue: acc -> smem transpose (stride 136) -> coalesced stores ----
    float* ep = reinterpret_cast<float*>(smem);
    #pragma unroll
    for (int mt = 0; mt < 2; mt++)
        #pragma unroll
        for (int nt = 0; nt < 4; nt++)
            #pragma unroll
            for (int e = 0; e < 4; e++) {
                int m = m0 + mt * 16 + (lane >> 2) + (e >> 1) * 8;
                int n = n0 + nt * 8 + (lane & 3) * 2 + (e & 1);
                float v = acc[mt][nt][e] + bias_sm[n];
                if (mode == 2) v = tanhf(v);
                ep[n * 136 + m] = v;
            }
    __syncthreads();

    #pragma unroll
    for (int i = 0; i < 8; i++) {
        int q   = tid + i * 512;
        int col = q >> 5;
        int f4  = q & 31;
        int m   = f4 * 4;
        float4 val = *reinterpret_cast<float4*>(ep + col * 136 + m);
        int cn = bn + col;
        int t  = t0 + (m >> 6);
        int b  = m & 63;
        float* dst;
        if (mode == 0)
            dst = g_iouT + (((size_t)t * 4 + (cn >> 9)) * 512 + (cn & 511)) * 64 + b;
        else if (mode == 1)
            dst = g_ctxT + ((size_t)t * 512 + cn) * 64 + b;
        else
            dst = g_wcsT + ((size_t)t * 512 + cn) * 64 + b;
        *reinterpret_cast<float4*>(dst) = val;
    }
}

// ---------------------------------------------------------------------------
// Persistent scan (R12 exact): kc-skewed weights, FFMA2, flat atomic barrier.
// ---------------------------------------------------------------------------
#define SM4_FLOATS 8256
#define SM1_FLOATS 2080
#define SM4_BYTES  (SM4_FLOATS * 4)
#define SM1_BYTES  (SM1_FLOATS * 4)
#define BUF_BYTES  20480
#define SCAN_SMEM_BYTES (SM4_BYTES + SM1_BYTES + BUF_BYTES)   /* 61824 */

__global__ void __launch_bounds__(256) scan_kernel(
    const float* __restrict__ W_iouh, const float* __restrict__ b_iouh,
    const float* __restrict__ W_fh,   const float* __restrict__ b_fh,
    const float* __restrict__ c0,     float* __restrict__ out)
{
    extern __shared__ char smraw[];
    float4* sm4w = reinterpret_cast<float4*>(smraw);
    float2* sm1w = reinterpret_cast<float2*>(smraw + SM4_BYTES);
    ull*    buf  = reinterpret_cast<ull*>(smraw + SM4_BYTES + SM1_BYTES);

    const int tid  = threadIdx.x;
    const int warp = tid >> 5;
    const int lane = tid & 31;
    const int mp   = warp >> 2;
    const int iq   = warp & 3;
    const int kc   = lane >> 3;
    const int bq   = lane & 7;
    const int blk  = blockIdx.x;

    for (int idx = tid; idx < 2048; idx += 256) {
        int ml = idx >> 9;
        int k  = idx & 511;
        int mg = blk * 4 + ml;
        sm4w[ml * 516 + (k >> 7) * 129 + (k & 127)] = make_float4(
            W_iouh[(size_t)mg * 512 + k],
            W_iouh[(size_t)(512 + mg) * 512 + k],
            W_iouh[(size_t)(1024 + mg) * 512 + k],
            W_iouh[(size_t)(1536 + mg) * 512 + k]);
    }
    for (int idx = tid; idx < 1024; idx += 256) {
        int mpp = idx >> 9;
        int k   = idx & 511;
        int mg0 = blk * 4 + 2 * mpp;
        sm1w[mpp * 520 + (k >> 7) * 130 + (k & 127)] =
            make_float2(W_fh[(size_t)mg0 * 512 + k], W_fh[(size_t)(mg0 + 1) * 512 + k]);
    }
    __syncthreads();

    const int m_own = tid >> 5;
    const int b0    = 2 * (tid & 31);
    const int m_g   = blk * 4 + m_own;
    const int mp_o  = m_own >> 1;
    const int ml_o  = m_own & 1;
    int bq_o, pr_o;
    if (b0 < 32) { bq_o = b0 >> 2; pr_o = (b0 >> 1) & 1; }
    else         { int bb = b0 - 32; bq_o = bb >> 2; pr_o = 2 + ((bb >> 1) & 1); }

    float bfv = 0.f, biv = 0.f, bov = 0.f, bocv = 0.f, bfhv = 0.f;
    float2 c_reg = make_float2(0.f, 0.f);
    float2 af2, ai2, ao2, aoc2, act2, aw2;
    if (tid < 128) {
        bfv  = b_iouh[m_g];
        biv  = b_iouh[512 + m_g];
        bov  = b_iouh[1024 + m_g];
        bocv = b_iouh[1536 + m_g];
        bfhv = b_fh[m_g];
        c_reg.x = c0[(size_t)b0 * 512 + m_g];
        c_reg.y = c0[(size_t)(b0 + 1) * 512 + m_g];
        const size_t ib = ((size_t)0 * 4 * 512 + m_g) * 64 + b0;
        const size_t sb = (size_t)m_g * 64 + b0;
        af2  = *reinterpret_cast<const float2*>(&g_iouT[ib]);
        ai2  = *reinterpret_cast<const float2*>(&g_iouT[ib + 1 * 512 * 64]);
        ao2  = *reinterpret_cast<const float2*>(&g_iouT[ib + 2 * 512 * 64]);
        aoc2 = *reinterpret_cast<const float2*>(&g_iouT[ib + 3 * 512 * 64]);
        act2 = *reinterpret_cast<const float2*>(&g_ctxT[sb]);
        aw2  = *reinterpret_cast<const float2*>(&g_wcsT[sb]);
    }

    const int kbase = kc * 128 + iq * 32;
    const int fbase = kbase * 16 + bq;
    const int w4base = kc * 129 + iq * 32;
    const int w1base = kc * 130 + iq * 32;
    float2 h_keep = make_float2(0.f, 0.f);

    for (int t = 0; t < SEQ_T; t++) {
        const float* hb = (t == 0) ? g_h0T : (g_hT + (size_t)(t - 1) * (DIM * NB));
        const float4* hp = reinterpret_cast<const float4*>(hb);

        ull A[2][5][4];
        #pragma unroll
        for (int a1 = 0; a1 < 2; a1++)
            #pragma unroll
            for (int a2 = 0; a2 < 5; a2++)
                #pragma unroll
                for (int a3 = 0; a3 < 4; a3++) A[a1][a2][a3] = 0ull;

        #pragma unroll 4
        for (int i = 0; i < 32; i++) {
            float4 hl = __ldg(hp + fbase + i * 16);
            float4 hh = __ldg(hp + fbase + 8 + i * 16);
            ull hpair[4];
            hpair[0] = reinterpret_cast<ulonglong2*>(&hl)->x;
            hpair[1] = reinterpret_cast<ulonglong2*>(&hl)->y;
            hpair[2] = reinterpret_cast<ulonglong2*>(&hh)->x;
            hpair[3] = reinterpret_cast<ulonglong2*>(&hh)->y;

            float wa[10];
            *reinterpret_cast<float4*>(wa + 0) = sm4w[(mp * 2 + 0) * 516 + w4base + i];
            *reinterpret_cast<float4*>(wa + 4) = sm4w[(mp * 2 + 1) * 516 + w4base + i];
            *reinterpret_cast<float2*>(wa + 8) = sm1w[mp * 520 + w1base + i];

            #pragma unroll
            for (int ml = 0; ml < 2; ml++) {
                #pragma unroll
                for (int g = 0; g < 5; g++) {
                    float w = (g < 4) ? wa[ml * 4 + g] : wa[8 + ml];
                    ull wd = packdup(w);
                    #pragma unroll
                    for (int pr = 0; pr < 4; pr++)
                        ffma2(A[ml][g][pr], hpair[pr], wd);
                }
            }
        }

        ull* Af = &A[0][0][0];
        #pragma unroll
        for (int c = 0; c < 40; c++) {
            float2 v = *reinterpret_cast<float2*>(&Af[c]);
            v.x += __shfl_xor_sync(0xffffffffu, v.x, 8);
            v.y += __shfl_xor_sync(0xffffffffu, v.y, 8);
            v.x += __shfl_xor_sync(0xffffffffu, v.x, 16);
            v.y += __shfl_xor_sync(0xffffffffu, v.y, 16);
            Af[c] = *reinterpret_cast<ull*>(&v);
        }

        #pragma unroll
        for (int cc = 0; cc < 10; cc++) {
            int c = kc * 10 + cc;
            buf[((size_t)warp * 40 + c) * 8 + bq] = Af[c];
        }
        __syncthreads();

        if (tid < 128) {
            float2 s[5];
            #pragma unroll
            for (int g = 0; g < 5; g++) {
                int c = ml_o * 20 + g * 4 + pr_o;
                float2 acc2 = make_float2(0.f, 0.f);
                #pragma unroll
                for (int q = 0; q < 4; q++) {
                    ull v = buf[((size_t)(mp_o * 4 + q) * 40 + c) * 8 + bq_o];
                    float2 f = *reinterpret_cast<float2*>(&v);
                    acc2.x += f.x; acc2.y += f.y;
                }
                s[g] = acc2;
            }

            float fgx  = sigmoid_fast(s[0].x + af2.x + bfv);
            float fgy  = sigmoid_fast(s[0].y + af2.y + bfv);
            float igx  = sigmoid_fast(s[1].x + ai2.x + biv);
            float igy  = sigmoid_fast(s[1].y + ai2.y + biv);
            float ogx  = sigmoid_fast(s[2].x + ao2.x + bov);
            float ogy  = sigmoid_fast(s[2].y + ao2.y + bov);
            float ocgx = sigmoid_fast(s[3].x + aoc2.x + bocv);
            float ocgy = sigmoid_fast(s[3].y + aoc2.y + bocv);
            float ctx_ = tanh_fast(s[4].x + act2.x + bfhv);
            float cty_ = tanh_fast(s[4].y + act2.y + bfhv);

            c_reg.x = igx * ctx_ + fgx * c_reg.x;
            c_reg.y = igy * cty_ + fgy * c_reg.y;
            h_keep.x = ogx * tanh_fast(c_reg.x) + ocgx * aw2.x;
            h_keep.y = ogy * tanh_fast(c_reg.y) + ocgy * aw2.y;

            *reinterpret_cast<float2*>(&g_hT[(size_t)t * (DIM * NB) + (size_t)m_g * 64 + b0]) = h_keep;
            out[(size_t)t * (NB * DIM) + (size_t)b0 * 512 + m_g]       = h_keep.x;
            out[(size_t)t * (NB * DIM) + (size_t)(b0 + 1) * 512 + m_g] = h_keep.y;

            if (t + 1 < SEQ_T) {
                const size_t ib2 = (((size_t)(t + 1) * 4) * 512 + m_g) * 64 + b0;
                const size_t sb2 = (size_t)(t + 1) * (512 * 64) + (size_t)m_g * 64 + b0;
                af2  = *reinterpret_cast<const float2*>(&g_iouT[ib2]);
                ai2  = *reinterpret_cast<const float2*>(&g_iouT[ib2 + 1 * 512 * 64]);
                ao2  = *reinterpret_cast<const float2*>(&g_iouT[ib2 + 2 * 512 * 64]);
                aoc2 = *reinterpret_cast<const float2*>(&g_iouT[ib2 + 3 * 512 * 64]);
                act2 = *reinterpret_cast<const float2*>(&g_ctxT[sb2]);
                aw2  = *reinterpret_cast<const float2*>(&g_wcsT[sb2]);
            }
        }

        __syncthreads();
        if (tid == 0) {
            __threadfence();
            atomicAdd(&g_cnt, 1u);
            const unsigned target = (unsigned)gridDim.x * (unsigned)(t + 1);
            while (*reinterpret_cast<volatile unsigned*>(&g_cnt) < target) { }
            __threadfence();
        }
        __syncthreads();
    }

    if (tid < 128) {
        out[TBM + (size_t)b0 * 512 + m_g]                  = c_reg.x;
        out[TBM + (size_t)(b0 + 1) * 512 + m_g]            = c_reg.y;
        out[TBM + NB * DIM + (size_t)b0 * 512 + m_g]       = h_keep.x;
        out[TBM + NB * DIM + (size_t)(b0 + 1) * 512 + m_g] = h_keep.y;
    }
}

// ---------------------------------------------------------------------------
extern "C" void kernel_launch(void* const* d_in, const int* in_sizes, int n_in,
                              void* d_out, int out_size)
{
    const float* inputs = (const float*)d_in[0];
    const float* emb_s  = (const float*)d_in[1];
    const float* c0     = (const float*)d_in[2];
    const float* h0     = (const float*)d_in[3];
    const float* W_ioux = (const float*)d_in[4];
    const float* b_ioux = (const float*)d_in[5];
    const float* W_iouh = (const float*)d_in[6];
    const float* b_iouh = (const float*)d_in[7];
    const float* W_ious = (const float*)d_in[8];
    const float* b_ious = (const float*)d_in[9];
    const float* W_fx   = (const float*)d_in[10];
    const float* b_fx   = (const float*)d_in[11];
    const float* W_fh   = (const float*)d_in[12];
    const float* b_fh   = (const float*)d_in[13];
    const float* W_wc   = (const float*)d_in[14];
    const float* b_wc   = (const float*)d_in[15];
    float* out = (float*)d_out;

    static int smem_set = 0;
    if (!smem_set) {
        cudaFuncSetAttribute(scan_kernel, cudaFuncAttributeMaxDynamicSharedMemorySize,
                             SCAN_SMEM_BYTES);
        cudaFuncSetAttribute(gemm_tc_kernel, cudaFuncAttributeMaxDynamicSharedMemorySize,
                             G_SMEM_TOTAL);
        smem_set = 1;
    }

    conv_init_kernel<<<19008, 256>>>(inputs, emb_s, W_ioux, W_ious, W_fx, W_wc, h0);
    gemm_tc_kernel<<<3072, 512, G_SMEM_TOTAL>>>(b_ioux, b_ious, b_fx, b_wc);
    scan_kernel<<<128, 256, SCAN_SMEM_BYTES>>>(W_iouh, b_iouh, W_fh, b_fh, c0, out);
}